// round 5
// baseline (speedup 1.0000x reference)
#include <cuda_runtime.h>
#include <math.h>

// ---------------------------------------------------------------------------
// Shapes: B=32, OBS=768, D=512, V=64
// Outputs (float32, concatenated): h(32*512) pred(32*768) graph(64*64) reasoning(32*512)
// ---------------------------------------------------------------------------

#define NB 32
#define NOBS 768
#define ND 512
#define NV 64

// scratch layout (floats)
#define OFF_T1   0          // 32*1024
#define OFF_X    32768      // 32*1024  ([z, action])
#define OFF_GI   65536      // 32*1536
#define OFF_H    114688     // 32*512
#define OFF_HA   131072     // 32*512
#define OFF_CC   147456     // 32*1024
#define OFF_EA   180224     // 64*1024  (Ea + sc_b1 folded)
#define OFF_EB   245760     // 64*1024
#define OFF_R1   311296     // 32*512
#define OFF_DA   327680     // 64
#define OFF_DB   327744     // 64
#define OFF_DC   327808     // 32
#define SCRATCH_FLOATS 327936

__device__ float g_scratch[SCRATCH_FLOATS];

// ---------------------------------------------------------------------------
// helpers
// ---------------------------------------------------------------------------
__device__ __forceinline__ float tanh_approx(float x) {
    float y;
    asm("tanh.approx.f32 %0, %1;" : "=f"(y) : "f"(x));
    return y;
}
__device__ __forceinline__ float sigmoid_acc(float x) {
    return 1.0f / (1.0f + expf(-x));
}
__device__ __forceinline__ float gelu_exact(float x) {
    return 0.5f * x * (1.0f + erff(x * 0.70710678118654752f));
}

// ---------------------------------------------------------------------------
// Generic skinny GEMM: C[m,n] = act( sum_k A[m,k] * W[n, woff+k] + bias[n] )
// M == MP (32 or 64). 256 threads. Each thread owns one (m, n) output.
// A chunk staged in smem (pitch 129 -> conflict-free lane reads);
// W streamed once via warp-uniform LDG.128.
// ---------------------------------------------------------------------------
template<int MP, bool GELU>
__global__ void __launch_bounds__(256) gemm_nt(
    const float* __restrict__ A, int lda,
    const float* __restrict__ W, int ldw, int woff,
    const float* __restrict__ bias,
    float* __restrict__ C, int ldc, int N, int K)
{
    constexpr int TN = 256 / MP;
    __shared__ float sA[MP][129];
    const int m  = threadIdx.x % MP;
    const int ns = threadIdx.x / MP;
    const int n  = blockIdx.x * TN + ns;

    float a0 = 0.f, a1 = 0.f, a2 = 0.f, a3 = 0.f;
    const float* wp = W + (size_t)n * ldw + woff;

    for (int k0 = 0; k0 < K; k0 += 128) {
        // stage A chunk: [MP][128]
        for (int idx = threadIdx.x; idx < MP * 128; idx += 256) {
            int mm = idx >> 7, kk = idx & 127;
            sA[mm][kk] = A[mm * lda + k0 + kk];
        }
        __syncthreads();
        if (n < N) {
            #pragma unroll
            for (int kk = 0; kk < 128; kk += 4) {
                float4 w4 = *reinterpret_cast<const float4*>(wp + k0 + kk);
                a0 = fmaf(sA[m][kk + 0], w4.x, a0);
                a1 = fmaf(sA[m][kk + 1], w4.y, a1);
                a2 = fmaf(sA[m][kk + 2], w4.z, a2);
                a3 = fmaf(sA[m][kk + 3], w4.w, a3);
            }
        }
        __syncthreads();
    }
    if (n < N) {
        float v = (a0 + a1) + (a2 + a3);
        if (bias) v += bias[n];
        if (GELU) v = gelu_exact(v);
        C[m * ldc + n] = v;
    }
}

// ---------------------------------------------------------------------------
// misc small kernels
// ---------------------------------------------------------------------------
__global__ void zero_graph_kernel(float* __restrict__ graph) {
    int i = blockIdx.x * blockDim.x + threadIdx.x;
    if (i < NV * NV) graph[i] = 0.0f;
}

__global__ void copy_action_kernel(const float* __restrict__ action, float* __restrict__ X) {
    int i = blockIdx.x * blockDim.x + threadIdx.x;
    if (i < NB * ND) {
        int b = i >> 9, d = i & 511;
        X[b * 1024 + 512 + d] = action[i];
    }
}

// GRU with h0 = 0:  gh = bhh.
__global__ void gru_kernel(const float* __restrict__ GI, const float* __restrict__ bhh,
                           const float* __restrict__ action,
                           float* __restrict__ H, float* __restrict__ HA,
                           float* __restrict__ out_h)
{
    int i = blockIdx.x * blockDim.x + threadIdx.x;
    if (i >= NB * ND) return;
    int b = i >> 9, d = i & 511;
    const float* gi = GI + b * 1536;
    float r  = sigmoid_acc(gi[d]        + bhh[d]);
    float u  = sigmoid_acc(gi[512 + d]  + bhh[512 + d]);
    float nn = tanhf(gi[1024 + d] + r * bhh[1024 + d]);
    float h  = (1.0f - u) * nn;
    H[i] = h;
    out_h[i] = h;
    HA[i] = h + action[i];
}

// linear-part dots: da[i]=sum 0.5*w2*EA[i], db[j]=..., dc[b]=...
// 160 warps total -> 20 blocks x 256.
__global__ void dots_kernel(const float* __restrict__ EA, const float* __restrict__ EB,
                            const float* __restrict__ CC, const float* __restrict__ w2,
                            float* __restrict__ da, float* __restrict__ db, float* __restrict__ dc)
{
    int gw = (blockIdx.x * blockDim.x + threadIdx.x) >> 5;
    int lane = threadIdx.x & 31;
    if (gw >= 160) return;
    const float* src; float* dst;
    if (gw < 64)       { src = EA + gw * 1024;         dst = da + gw; }
    else if (gw < 128) { src = EB + (gw - 64) * 1024;  dst = db + (gw - 64); }
    else               { src = CC + (gw - 128) * 1024; dst = dc + (gw - 128); }
    float s = 0.f;
    for (int d = lane; d < 1024; d += 32) s = fmaf(0.5f * w2[d], src[d], s);
    #pragma unroll
    for (int off = 16; off > 0; off >>= 1) s += __shfl_xor_sync(0xffffffffu, s, off);
    if (lane == 0) *dst = s;
}

// ---------------------------------------------------------------------------
// Score kernel: graph[i,j] = mean_b sigmoid( sum_d w2[d]*gelu(x) + b2 )
//   x = CC[b,d] + EA[i,d] + EB[j,d]   (EA includes sc_b1)
// Split:  logit = dc[b]+da[i]+db[j] + b2 + sum_d (0.5*w2[d]*x) * tanh(t(x))
// Block: b fixed, 16 i-rows, 32 j (one per lane), 8 warps x 2 rows.
// Grid: (128, 2).
// ---------------------------------------------------------------------------
__global__ void __launch_bounds__(256) score_kernel(
    const float* __restrict__ EA, const float* __restrict__ EB,
    const float* __restrict__ CC,
    const float* __restrict__ da, const float* __restrict__ db,
    const float* __restrict__ dc,
    const float* __restrict__ w2, const float* __restrict__ b2p,
    float* __restrict__ graph)
{
    __shared__ float sE[128][33];   // EbT chunk: [dd][j]
    __shared__ float sA[16][128];   // EA[i]+CC[b] chunk (broadcast reads)
    __shared__ float sW[128];       // 0.5*w2 chunk

    const int g  = blockIdx.x;          // 0..127
    const int b  = g >> 2;
    const int i0 = (g & 3) * 16;
    const int j0 = blockIdx.y * 32;

    const int warp = threadIdx.x >> 5;
    const int lane = threadIdx.x & 31;
    const int r0 = warp * 2, r1 = warp * 2 + 1;

    float acc0 = 0.f, acc1 = 0.f;

    const float C0 = 0.79788456080286536f;   // sqrt(2/pi)
    const float C1 = 0.03567740813636141f;   // sqrt(2/pi)*0.044715

    for (int d0 = 0; d0 < 1024; d0 += 128) {
        for (int idx = threadIdx.x; idx < 32 * 128; idx += 256) {
            int j = idx >> 7, dd = idx & 127;
            sE[dd][j] = EB[(j0 + j) * 1024 + d0 + dd];
        }
        for (int idx = threadIdx.x; idx < 16 * 128; idx += 256) {
            int r = idx >> 7, dd = idx & 127;
            sA[r][dd] = EA[(i0 + r) * 1024 + d0 + dd] + CC[b * 1024 + d0 + dd];
        }
        if (threadIdx.x < 128) sW[threadIdx.x] = 0.5f * w2[d0 + threadIdx.x];
        __syncthreads();

        #pragma unroll 4
        for (int dd = 0; dd < 128; dd++) {
            float e = sE[dd][lane];
            float w = sW[dd];
            float a0v = sA[r0][dd];
            float a1v = sA[r1][dd];

            float x0 = a0v + e;
            float x1 = a1v + e;
            float t0 = x0 * fmaf(C1, x0 * x0, C0);
            float t1 = x1 * fmaf(C1, x1 * x1, C0);
            float u0 = tanh_approx(t0);
            float u1 = tanh_approx(t1);
            acc0 = fmaf(w * x0, u0, acc0);
            acc1 = fmaf(w * x1, u1, acc1);
        }
        __syncthreads();
    }

    const float b2 = b2p[0];
    const float Lj = db[j0 + lane];
    const float Lb = dc[b];

    float lg0 = acc0 + da[i0 + r0] + Lj + Lb + b2;
    float lg1 = acc1 + da[i0 + r1] + Lj + Lb + b2;
    float s0 = sigmoid_acc(lg0) * (1.0f / 32.0f);
    float s1 = sigmoid_acc(lg1) * (1.0f / 32.0f);

    atomicAdd(&graph[(i0 + r0) * 64 + j0 + lane], s0);
    atomicAdd(&graph[(i0 + r1) * 64 + j0 + lane], s1);
}

// ---------------------------------------------------------------------------
// launch
// ---------------------------------------------------------------------------
extern "C" void kernel_launch(void* const* d_in, const int* in_sizes, int n_in,
                              void* d_out, int out_size)
{
    float* S = nullptr;
    cudaGetSymbolAddress((void**)&S, g_scratch);

    const float* obs     = (const float*)d_in[0];
    const float* action  = (const float*)d_in[1];
    const float* embed   = (const float*)d_in[2];
    const float* sc_w1   = (const float*)d_in[3];
    const float* sc_b1   = (const float*)d_in[4];
    const float* sc_w2   = (const float*)d_in[5];
    const float* sc_b2   = (const float*)d_in[6];
    const float* enc_w1  = (const float*)d_in[7];
    const float* enc_b1  = (const float*)d_in[8];
    const float* enc_w2  = (const float*)d_in[9];
    const float* enc_b2  = (const float*)d_in[10];
    const float* gru_wih = (const float*)d_in[11];
    // d_in[12] gru_whh: unused (h0 == 0)
    const float* gru_bih = (const float*)d_in[13];
    const float* gru_bhh = (const float*)d_in[14];
    const float* dec_w   = (const float*)d_in[15];
    const float* dec_b   = (const float*)d_in[16];
    const float* rs_w1   = (const float*)d_in[17];
    const float* rs_b1   = (const float*)d_in[18];
    const float* rs_w2   = (const float*)d_in[19];
    const float* rs_b2   = (const float*)d_in[20];

    float* out        = (float*)d_out;
    float* out_h      = out;                       // 32*512
    float* out_pred   = out + 16384;               // 32*768
    float* out_graph  = out + 16384 + 24576;       // 64*64
    float* out_reason = out + 16384 + 24576 + 4096;// 32*512

    float* T1 = S + OFF_T1;
    float* X  = S + OFF_X;
    float* GI = S + OFF_GI;
    float* H  = S + OFF_H;
    float* HA = S + OFF_HA;
    float* CC = S + OFF_CC;
    float* EA = S + OFF_EA;
    float* EB = S + OFF_EB;
    float* R1 = S + OFF_R1;
    float* da = S + OFF_DA;
    float* db = S + OFF_DB;
    float* dc = S + OFF_DC;

    zero_graph_kernel<<<16, 256>>>(out_graph);

    // encoder
    gemm_nt<32, true ><<<128, 256>>>(obs, 768, enc_w1, 768, 0, enc_b1, T1, 1024, 1024, 768);
    gemm_nt<32, false><<< 64, 256>>>(T1, 1024, enc_w2, 1024, 0, enc_b2, X, 1024, 512, 1024);
    copy_action_kernel<<<64, 256>>>(action, X);

    // GRU (h0 = 0)
    gemm_nt<32, false><<<192, 256>>>(X, 1024, gru_wih, 1024, 0, gru_bih, GI, 1536, 1536, 1024);
    gru_kernel<<<64, 256>>>(GI, gru_bhh, action, H, HA, out_h);

    // decoder + reasoning
    gemm_nt<32, false><<< 96, 256>>>(H, 512, dec_w, 512, 0, dec_b, out_pred, 768, 768, 512);
    gemm_nt<32, true ><<< 64, 256>>>(H, 512, rs_w1, 512, 0, rs_b1, R1, 512, 512, 512);
    gemm_nt<32, false><<< 64, 256>>>(R1, 512, rs_w2, 512, 0, rs_b2, out_reason, 512, 512, 512);

    // score-path projections (sc_w1 columns: [Wa | Wb | Wc], ldw = 1536)
    gemm_nt<64, false><<<256, 256>>>(embed, 512, sc_w1, 1536,    0, sc_b1,   EA, 1024, 1024, 512);
    gemm_nt<64, false><<<256, 256>>>(embed, 512, sc_w1, 1536,  512, nullptr, EB, 1024, 1024, 512);
    gemm_nt<32, false><<<128, 256>>>(HA,    512, sc_w1, 1536, 1024, nullptr, CC, 1024, 1024, 512);

    dots_kernel<<<20, 256>>>(EA, EB, CC, sc_w2, da, db, dc);

    score_kernel<<<dim3(128, 2), 256>>>(EA, EB, CC, da, db, dc, sc_w2, sc_b2, out_graph);
}

// round 6
// speedup vs baseline: 2.0001x; 2.0001x over previous
#include <cuda_runtime.h>
#include <math.h>

// ---------------------------------------------------------------------------
// Shapes: B=32, OBS=768, D=512, V=64
// Outputs (float32): h(32*512) pred(32*768) graph(64*64) reasoning(32*512)
// 5-kernel schedule:
//  K1: enc1(T1) + EA + EB + zero(graph)          [independent]
//  K2: enc2 (T1 -> Z)
//  K3: fused GI GEMM + GRU pointwise -> H, HA    (no concat, no GI tensor)
//  K4: dec(pred) + rs1(R1) + CC                  [all need H/HA]
//  K5: rs2(reasoning) + score (linear term folded into main loop)
// ---------------------------------------------------------------------------

#define NB 32
#define ND 512
#define NV 64

// scratch (floats)
#define OFF_T1   0          // 32*1024
#define OFF_Z    32768      // 32*512
#define OFF_H    49152      // 32*512
#define OFF_HA   65536      // 32*512
#define OFF_CC   81920      // 32*1024
#define OFF_EA   114688     // 64*1024 (Ea + sc_b1 folded)
#define OFF_EB   180224     // 64*1024
#define OFF_R1   245760     // 32*512
#define SCRATCH_FLOATS 262144

__device__ float g_scratch[SCRATCH_FLOATS];

// ---------------------------------------------------------------------------
__device__ __forceinline__ float tanh_approx(float x) {
    float y;
    asm("tanh.approx.f32 %0, %1;" : "=f"(y) : "f"(x));
    return y;
}
__device__ __forceinline__ float sigmoid_acc(float x) {
    return 1.0f / (1.0f + expf(-x));
}
__device__ __forceinline__ float gelu_exact(float x) {
    return 0.5f * x * (1.0f + erff(x * 0.70710678118654752f));
}

// ---------------------------------------------------------------------------
// Skinny GEMM device function: C[m,n] = act( sum_k A[m,k]*W[n,woff+k] + bias[n] )
// 256 threads; thread owns one (m,n). A chunk staged in smem (pitch 129);
// W streamed via warp-uniform LDG.128 (n is constant within a warp).
// ---------------------------------------------------------------------------
template<int MP, bool GELU>
__device__ __forceinline__ void gemm_dev(
    float* pool, int bid,
    const float* __restrict__ A, int lda,
    const float* __restrict__ W, int ldw, int woff,
    const float* __restrict__ bias,
    float* __restrict__ C, int ldc, int N, int K)
{
    float (*sA)[129] = (float (*)[129])pool;
    const int m  = threadIdx.x % MP;
    const int ns = threadIdx.x / MP;
    const int n  = bid * (256 / MP) + ns;

    float a0 = 0.f, a1 = 0.f, a2 = 0.f, a3 = 0.f;
    const float* wp = W + (size_t)n * ldw + woff;

    for (int k0 = 0; k0 < K; k0 += 128) {
        for (int idx = threadIdx.x; idx < MP * 128; idx += 256) {
            int mm = idx >> 7, kk = idx & 127;
            sA[mm][kk] = A[mm * lda + k0 + kk];
        }
        __syncthreads();
        if (n < N) {
            #pragma unroll
            for (int kk = 0; kk < 128; kk += 4) {
                float4 w4 = *reinterpret_cast<const float4*>(wp + k0 + kk);
                a0 = fmaf(sA[m][kk + 0], w4.x, a0);
                a1 = fmaf(sA[m][kk + 1], w4.y, a1);
                a2 = fmaf(sA[m][kk + 2], w4.z, a2);
                a3 = fmaf(sA[m][kk + 3], w4.w, a3);
            }
        }
        __syncthreads();
    }
    if (n < N) {
        float v = (a0 + a1) + (a2 + a3);
        if (bias) v += bias[n];
        if (GELU) v = gelu_exact(v);
        C[m * ldc + n] = v;
    }
}

// ---------------------------------------------------------------------------
// K1: enc1 (128 blk) + EA (256 blk) + EB (256 blk) + zero graph (1 blk)
// ---------------------------------------------------------------------------
__global__ void __launch_bounds__(256) k1_kernel(
    const float* __restrict__ obs, const float* __restrict__ enc_w1,
    const float* __restrict__ enc_b1, float* __restrict__ T1,
    const float* __restrict__ embed, const float* __restrict__ sc_w1,
    const float* __restrict__ sc_b1,
    float* __restrict__ EA, float* __restrict__ EB,
    float* __restrict__ graph)
{
    __shared__ float pool[64 * 129];
    int b = blockIdx.x;
    if (b < 128) {
        gemm_dev<32, true>(pool, b, obs, 768, enc_w1, 768, 0, enc_b1, T1, 1024, 1024, 768);
    } else if (b < 384) {
        gemm_dev<64, false>(pool, b - 128, embed, 512, sc_w1, 1536, 0, sc_b1, EA, 1024, 1024, 512);
    } else if (b < 640) {
        gemm_dev<64, false>(pool, b - 384, embed, 512, sc_w1, 1536, 512, nullptr, EB, 1024, 1024, 512);
    } else {
        for (int i = threadIdx.x; i < NV * NV; i += 256) graph[i] = 0.0f;
    }
}

// ---------------------------------------------------------------------------
// K2: enc2 (T1 -> Z), 64 blocks
// ---------------------------------------------------------------------------
__global__ void __launch_bounds__(256) k2_kernel(
    const float* __restrict__ T1, const float* __restrict__ enc_w2,
    const float* __restrict__ enc_b2, float* __restrict__ Z)
{
    __shared__ float pool[32 * 129];
    gemm_dev<32, false>(pool, blockIdx.x, T1, 1024, enc_w2, 1024, 0, enc_b2, Z, 512, 512, 1024);
}

// ---------------------------------------------------------------------------
// K3: fused GI + GRU. 64 blocks x 256 threads.
// Thread (m = tid%32 -> batch, ns = tid/32 -> d = blk*8+ns) computes all
// three gate dots over k=[z(512); action(512)] and applies the GRU directly.
// h0 = 0 => gh = bhh, h = (1-u)*n.
// ---------------------------------------------------------------------------
__global__ void __launch_bounds__(256) k3_kernel(
    const float* __restrict__ Z, const float* __restrict__ action,
    const float* __restrict__ gru_wih,
    const float* __restrict__ bih, const float* __restrict__ bhh,
    float* __restrict__ H, float* __restrict__ HA, float* __restrict__ out_h)
{
    __shared__ float sX[32][129];
    const int m  = threadIdx.x % 32;
    const int ns = threadIdx.x / 32;
    const int d  = blockIdx.x * 8 + ns;

    float r0 = 0.f, r1 = 0.f;   // r gate
    float u0 = 0.f, u1 = 0.f;   // u gate
    float n0 = 0.f, n1 = 0.f;   // n gate

    const float* wr = gru_wih + (size_t)(d) * 1024;
    const float* wu = gru_wih + (size_t)(512 + d) * 1024;
    const float* wn = gru_wih + (size_t)(1024 + d) * 1024;

    for (int k0 = 0; k0 < 1024; k0 += 128) {
        const float* src = (k0 < 512) ? (Z + k0) : (action + (k0 - 512));
        for (int idx = threadIdx.x; idx < 32 * 128; idx += 256) {
            int mm = idx >> 7, kk = idx & 127;
            sX[mm][kk] = src[mm * 512 + kk];
        }
        __syncthreads();
        #pragma unroll
        for (int kk = 0; kk < 128; kk += 4) {
            float4 wr4 = *reinterpret_cast<const float4*>(wr + k0 + kk);
            float4 wu4 = *reinterpret_cast<const float4*>(wu + k0 + kk);
            float4 wn4 = *reinterpret_cast<const float4*>(wn + k0 + kk);
            float x0 = sX[m][kk + 0], x1 = sX[m][kk + 1];
            float x2 = sX[m][kk + 2], x3 = sX[m][kk + 3];
            r0 = fmaf(x0, wr4.x, r0);  r1 = fmaf(x1, wr4.y, r1);
            r0 = fmaf(x2, wr4.z, r0);  r1 = fmaf(x3, wr4.w, r1);
            u0 = fmaf(x0, wu4.x, u0);  u1 = fmaf(x1, wu4.y, u1);
            u0 = fmaf(x2, wu4.z, u0);  u1 = fmaf(x3, wu4.w, u1);
            n0 = fmaf(x0, wn4.x, n0);  n1 = fmaf(x1, wn4.y, n1);
            n0 = fmaf(x2, wn4.z, n0);  n1 = fmaf(x3, wn4.w, n1);
        }
        __syncthreads();
    }

    float gr = (r0 + r1) + bih[d]        + bhh[d];
    float gu = (u0 + u1) + bih[512 + d]  + bhh[512 + d];
    float r  = sigmoid_acc(gr);
    float u  = sigmoid_acc(gu);
    float nn = tanhf((n0 + n1) + bih[1024 + d] + r * bhh[1024 + d]);
    float h  = (1.0f - u) * nn;

    int o = m * 512 + d;
    H[o] = h;
    out_h[o] = h;
    HA[o] = h + action[o];
}

// ---------------------------------------------------------------------------
// K4: dec (96 blk) + rs1 (64 blk) + CC (128 blk) = 288 blocks
// ---------------------------------------------------------------------------
__global__ void __launch_bounds__(256) k4_kernel(
    const float* __restrict__ H, const float* __restrict__ HA,
    const float* __restrict__ dec_w, const float* __restrict__ dec_b,
    float* __restrict__ pred,
    const float* __restrict__ rs_w1, const float* __restrict__ rs_b1,
    float* __restrict__ R1,
    const float* __restrict__ sc_w1, float* __restrict__ CC)
{
    __shared__ float pool[32 * 129];
    int b = blockIdx.x;
    if (b < 96) {
        gemm_dev<32, false>(pool, b, H, 512, dec_w, 512, 0, dec_b, pred, 768, 768, 512);
    } else if (b < 160) {
        gemm_dev<32, true>(pool, b - 96, H, 512, rs_w1, 512, 0, rs_b1, R1, 512, 512, 512);
    } else {
        gemm_dev<32, false>(pool, b - 160, HA, 512, sc_w1, 1536, 1024, nullptr, CC, 1024, 1024, 512);
    }
}

// ---------------------------------------------------------------------------
// K5: rs2 (64 blk) + score (128 blk) = 192 blocks
// Score: graph[i,j] += (1/32) * sigmoid( sum_d w2*gelu(x) + b2 ), x = CC[b]+EA[i]+EB[j]
//   gelu(x) ~ 0.5x + 0.5x*tanh(t(x));  both halves accumulated in-loop.
// Block: fixed b, 16 i-rows, all 64 j. 8 warps x 2 rows; lane covers j and j+32.
// ---------------------------------------------------------------------------
#define SC_POOL (128*65 + 16*128 + 128)    // sE + sA + sW = 10496 floats

__global__ void __launch_bounds__(256) k5_kernel(
    const float* __restrict__ R1, const float* __restrict__ rs_w2,
    const float* __restrict__ rs_b2, float* __restrict__ reason,
    const float* __restrict__ EA, const float* __restrict__ EB,
    const float* __restrict__ CC,
    const float* __restrict__ w2, const float* __restrict__ b2p,
    float* __restrict__ graph)
{
    __shared__ float pool[SC_POOL];
    int blk = blockIdx.x;
    if (blk < 64) {
        gemm_dev<32, false>(pool, blk, R1, 512, rs_w2, 512, 0, rs_b2, reason, 512, 512, 512);
        return;
    }
    const int sb = blk - 64;              // 0..127
    const int b  = sb >> 2;               // batch
    const int i0 = (sb & 3) * 16;         // i-row block

    float (*sE)[65] = (float (*)[65])pool;            // [dd][j] 128x65
    float (*sA)[128] = (float (*)[128])(pool + 128 * 65); // [r][dd] 16x128
    float* sW = pool + 128 * 65 + 16 * 128;           // [dd]

    const int warp = threadIdx.x >> 5;
    const int lane = threadIdx.x & 31;
    const int ra = warp * 2, rb = warp * 2 + 1;

    float acc0a = 0.f, acc0b = 0.f, acc1a = 0.f, acc1b = 0.f;
    float lin0a = 0.f, lin0b = 0.f, lin1a = 0.f, lin1b = 0.f;

    const float C0 = 0.79788456080286536f;   // sqrt(2/pi)
    const float C1 = 0.03567740813636141f;   // sqrt(2/pi)*0.044715

    for (int d0 = 0; d0 < 1024; d0 += 128) {
        for (int idx = threadIdx.x; idx < 64 * 128; idx += 256) {
            int j = idx >> 7, dd = idx & 127;
            sE[dd][j] = EB[j * 1024 + d0 + dd];
        }
        for (int idx = threadIdx.x; idx < 16 * 128; idx += 256) {
            int r = idx >> 7, dd = idx & 127;
            sA[r][dd] = EA[(i0 + r) * 1024 + d0 + dd] + CC[b * 1024 + d0 + dd];
        }
        if (threadIdx.x < 128) sW[threadIdx.x] = 0.5f * w2[d0 + threadIdx.x];
        __syncthreads();

        #pragma unroll 4
        for (int dd = 0; dd < 128; dd++) {
            float ea = sE[dd][lane];
            float eb = sE[dd][lane + 32];
            float w  = sW[dd];
            float a0 = sA[ra][dd];
            float a1 = sA[rb][dd];

            float x0a = a0 + ea, x0b = a0 + eb;
            float x1a = a1 + ea, x1b = a1 + eb;

            float t0a = x0a * fmaf(C1, x0a * x0a, C0);
            float t0b = x0b * fmaf(C1, x0b * x0b, C0);
            float t1a = x1a * fmaf(C1, x1a * x1a, C0);
            float t1b = x1b * fmaf(C1, x1b * x1b, C0);

            float h0a = tanh_approx(t0a);
            float h0b = tanh_approx(t0b);
            float h1a = tanh_approx(t1a);
            float h1b = tanh_approx(t1b);

            float wx0a = w * x0a, wx0b = w * x0b;
            float wx1a = w * x1a, wx1b = w * x1b;

            acc0a = fmaf(wx0a, h0a, acc0a);  lin0a += wx0a;
            acc0b = fmaf(wx0b, h0b, acc0b);  lin0b += wx0b;
            acc1a = fmaf(wx1a, h1a, acc1a);  lin1a += wx1a;
            acc1b = fmaf(wx1b, h1b, acc1b);  lin1b += wx1b;
        }
        __syncthreads();
    }

    const float b2 = b2p[0];
    float s0a = sigmoid_acc(acc0a + lin0a + b2) * (1.0f / 32.0f);
    float s0b = sigmoid_acc(acc0b + lin0b + b2) * (1.0f / 32.0f);
    float s1a = sigmoid_acc(acc1a + lin1a + b2) * (1.0f / 32.0f);
    float s1b = sigmoid_acc(acc1b + lin1b + b2) * (1.0f / 32.0f);

    atomicAdd(&graph[(i0 + ra) * 64 + lane],      s0a);
    atomicAdd(&graph[(i0 + ra) * 64 + lane + 32], s0b);
    atomicAdd(&graph[(i0 + rb) * 64 + lane],      s1a);
    atomicAdd(&graph[(i0 + rb) * 64 + lane + 32], s1b);
}

// ---------------------------------------------------------------------------
extern "C" void kernel_launch(void* const* d_in, const int* in_sizes, int n_in,
                              void* d_out, int out_size)
{
    float* S = nullptr;
    cudaGetSymbolAddress((void**)&S, g_scratch);

    const float* obs     = (const float*)d_in[0];
    const float* action  = (const float*)d_in[1];
    const float* embed   = (const float*)d_in[2];
    const float* sc_w1   = (const float*)d_in[3];
    const float* sc_b1   = (const float*)d_in[4];
    const float* sc_w2   = (const float*)d_in[5];
    const float* sc_b2   = (const float*)d_in[6];
    const float* enc_w1  = (const float*)d_in[7];
    const float* enc_b1  = (const float*)d_in[8];
    const float* enc_w2  = (const float*)d_in[9];
    const float* enc_b2  = (const float*)d_in[10];
    const float* gru_wih = (const float*)d_in[11];
    // d_in[12] gru_whh unused (h0 == 0)
    const float* gru_bih = (const float*)d_in[13];
    const float* gru_bhh = (const float*)d_in[14];
    const float* dec_w   = (const float*)d_in[15];
    const float* dec_b   = (const float*)d_in[16];
    const float* rs_w1   = (const float*)d_in[17];
    const float* rs_b1   = (const float*)d_in[18];
    const float* rs_w2   = (const float*)d_in[19];
    const float* rs_b2   = (const float*)d_in[20];

    float* out        = (float*)d_out;
    float* out_h      = out;                        // 32*512
    float* out_pred   = out + 16384;                // 32*768
    float* out_graph  = out + 16384 + 24576;        // 64*64
    float* out_reason = out + 16384 + 24576 + 4096; // 32*512

    float* T1 = S + OFF_T1;
    float* Z  = S + OFF_Z;
    float* H  = S + OFF_H;
    float* HA = S + OFF_HA;
    float* CC = S + OFF_CC;
    float* EA = S + OFF_EA;
    float* EB = S + OFF_EB;
    float* R1 = S + OFF_R1;

    k1_kernel<<<641, 256>>>(obs, enc_w1, enc_b1, T1, embed, sc_w1, sc_b1, EA, EB, out_graph);
    k2_kernel<<<64, 256>>>(T1, enc_w2, enc_b2, Z);
    k3_kernel<<<64, 256>>>(Z, action, gru_wih, gru_bih, gru_bhh, H, HA, out_h);
    k4_kernel<<<288, 256>>>(H, HA, dec_w, dec_b, out_pred, rs_w1, rs_b1, R1, sc_w1, CC);
    k5_kernel<<<192, 256>>>(R1, rs_w2, rs_b2, out_reason, EA, EB, CC, sc_w2, sc_b2, out_graph);
}

// round 10
// speedup vs baseline: 2.0946x; 1.0472x over previous
#include <cuda_runtime.h>
#include <math.h>

// ---------------------------------------------------------------------------
// Shapes: B=32, OBS=768, D=512, V=64
// Outputs (float32): h(32*512) pred(32*768) graph(64*64) reasoning(32*512)
// 5-kernel schedule (same dataflow as R6), GEMMs rebuilt for MLP=8:
//  K1: enc1(T1) + EA + EB + zero(graph)
//  K2: enc2 (T1 -> Z)                      128 blk x 128 thr
//  K3: fused GI GEMM + GRU -> H, HA        128 blk x 128 thr
//  K4: dec(pred) + rs1(R1) + CC
//  K5: rs2(reasoning) + score
// ---------------------------------------------------------------------------

#define NB 32
#define ND 512
#define NV 64

#define OFF_T1   0          // 32*1024
#define OFF_Z    32768      // 32*512
#define OFF_H    49152      // 32*512
#define OFF_HA   65536      // 32*512
#define OFF_CC   81920      // 32*1024
#define OFF_EA   114688     // 64*1024 (Ea + sc_b1 folded)
#define OFF_EB   180224     // 64*1024
#define OFF_R1   245760     // 32*512
#define SCRATCH_FLOATS 262144

__device__ float g_scratch[SCRATCH_FLOATS];

// ---------------------------------------------------------------------------
__device__ __forceinline__ float tanh_approx(float x) {
    float y;
    asm("tanh.approx.f32 %0, %1;" : "=f"(y) : "f"(x));
    return y;
}
__device__ __forceinline__ float sigmoid_acc(float x) {
    return 1.0f / (1.0f + expf(-x));
}
__device__ __forceinline__ float gelu_exact(float x) {
    return 0.5f * x * (1.0f + erff(x * 0.70710678118654752f));
}

// ---------------------------------------------------------------------------
// Skinny GEMM device fn, MLP=8: C[m,n] = act( sum_k A[m,k]*W[n,woff+k] + b[n] )
// NT threads; thread owns one (m,n); grids sized exactly (no n<N guard).
// W streamed in 32-k batches: 8 independent LDG.128 -> regs, then 32 FMAs.
// A chunk staged in smem (pitch 129, conflict-free).
// ---------------------------------------------------------------------------
template<int MP, int NT, bool GELU>
__device__ __forceinline__ void gemm_dev(
    float* pool, int bid,
    const float* __restrict__ A, int lda,
    const float* __restrict__ W, int ldw, int woff,
    const float* __restrict__ bias,
    float* __restrict__ C, int ldc, int K)
{
    float (*sA)[129] = (float (*)[129])pool;
    const int m  = threadIdx.x % MP;
    const int ns = threadIdx.x / MP;
    const int n  = bid * (NT / MP) + ns;

    float a0 = 0.f, a1 = 0.f, a2 = 0.f, a3 = 0.f;
    const float* wp = W + (size_t)n * ldw + woff;

    for (int k0 = 0; k0 < K; k0 += 128) {
        for (int idx = threadIdx.x; idx < MP * 128; idx += NT) {
            int mm = idx / 128, kk = idx & 127;
            sA[mm][kk] = A[mm * lda + k0 + kk];
        }
        __syncthreads();
        #pragma unroll
        for (int g = 0; g < 4; g++) {
            float4 w[8];
            #pragma unroll
            for (int i = 0; i < 8; i++)
                w[i] = *reinterpret_cast<const float4*>(wp + k0 + g * 32 + i * 4);
            #pragma unroll
            for (int i = 0; i < 8; i++) {
                int kk = g * 32 + i * 4;
                a0 = fmaf(sA[m][kk + 0], w[i].x, a0);
                a1 = fmaf(sA[m][kk + 1], w[i].y, a1);
                a2 = fmaf(sA[m][kk + 2], w[i].z, a2);
                a3 = fmaf(sA[m][kk + 3], w[i].w, a3);
            }
        }
        __syncthreads();
    }
    float v = (a0 + a1) + (a2 + a3);
    if (bias) v += bias[n];
    if (GELU) v = gelu_exact(v);
    C[m * ldc + n] = v;
}

// ---------------------------------------------------------------------------
// K1: enc1 (128 blk) + EA (256 blk) + EB (256 blk) + zero graph (1 blk) = 641
// ---------------------------------------------------------------------------
__global__ void __launch_bounds__(256) k1_kernel(
    const float* __restrict__ obs, const float* __restrict__ enc_w1,
    const float* __restrict__ enc_b1, float* __restrict__ T1,
    const float* __restrict__ embed, const float* __restrict__ sc_w1,
    const float* __restrict__ sc_b1,
    float* __restrict__ EA, float* __restrict__ EB,
    float* __restrict__ graph)
{
    __shared__ float pool[64 * 129];
    int b = blockIdx.x;
    if (b < 128) {
        gemm_dev<32, 256, true >(pool, b,       obs,   768, enc_w1, 768,   0, enc_b1, T1, 1024, 768);
    } else if (b < 384) {
        gemm_dev<64, 256, false>(pool, b - 128, embed, 512, sc_w1, 1536,   0, sc_b1,  EA, 1024, 512);
    } else if (b < 640) {
        gemm_dev<64, 256, false>(pool, b - 384, embed, 512, sc_w1, 1536, 512, nullptr,EB, 1024, 512);
    } else {
        for (int i = threadIdx.x; i < NV * NV; i += 256) graph[i] = 0.0f;
    }
}

// ---------------------------------------------------------------------------
// K2: enc2 (T1 -> Z). 128 blocks x 128 threads (4 n per block).
// ---------------------------------------------------------------------------
__global__ void __launch_bounds__(128) k2_kernel(
    const float* __restrict__ T1, const float* __restrict__ enc_w2,
    const float* __restrict__ enc_b2, float* __restrict__ Z)
{
    __shared__ float pool[32 * 129];
    gemm_dev<32, 128, false>(pool, blockIdx.x, T1, 1024, enc_w2, 1024, 0, enc_b2, Z, 512, 1024);
}

// ---------------------------------------------------------------------------
// K3: fused GI + GRU. 128 blocks x 128 threads.
// Thread (m = tid%32 -> batch, ns = tid/32 -> d = blk*4+ns) computes all
// three gate dots over k=[z(512); action(512)], 16-k batches (12 LDG.128 in
// flight), then applies GRU. h0=0 => gh=bhh, h=(1-u)*n.
// ---------------------------------------------------------------------------
__global__ void __launch_bounds__(128) k3_kernel(
    const float* __restrict__ Z, const float* __restrict__ action,
    const float* __restrict__ gru_wih,
    const float* __restrict__ bih, const float* __restrict__ bhh,
    float* __restrict__ H, float* __restrict__ HA, float* __restrict__ out_h)
{
    __shared__ float sX[32][129];
    const int m  = threadIdx.x % 32;
    const int ns = threadIdx.x / 32;
    const int d  = blockIdx.x * 4 + ns;

    float r0 = 0.f, r1 = 0.f, u0 = 0.f, u1 = 0.f, n0 = 0.f, n1 = 0.f;

    const float* wr = gru_wih + (size_t)(d) * 1024;
    const float* wu = gru_wih + (size_t)(512 + d) * 1024;
    const float* wn = gru_wih + (size_t)(1024 + d) * 1024;

    for (int k0 = 0; k0 < 1024; k0 += 128) {
        const float* src = (k0 < 512) ? (Z + k0) : (action + (k0 - 512));
        for (int idx = threadIdx.x; idx < 32 * 128; idx += 128) {
            int mm = idx >> 7, kk = idx & 127;
            sX[mm][kk] = src[mm * 512 + kk];
        }
        __syncthreads();
        #pragma unroll
        for (int g = 0; g < 8; g++) {
            float4 wr4[4], wu4[4], wn4[4];
            #pragma unroll
            for (int i = 0; i < 4; i++) {
                int kk = k0 + g * 16 + i * 4;
                wr4[i] = *reinterpret_cast<const float4*>(wr + kk);
                wu4[i] = *reinterpret_cast<const float4*>(wu + kk);
                wn4[i] = *reinterpret_cast<const float4*>(wn + kk);
            }
            #pragma unroll
            for (int i = 0; i < 4; i++) {
                int kk = g * 16 + i * 4;
                float x0 = sX[m][kk + 0], x1 = sX[m][kk + 1];
                float x2 = sX[m][kk + 2], x3 = sX[m][kk + 3];
                r0 = fmaf(x0, wr4[i].x, r0);  r1 = fmaf(x1, wr4[i].y, r1);
                r0 = fmaf(x2, wr4[i].z, r0);  r1 = fmaf(x3, wr4[i].w, r1);
                u0 = fmaf(x0, wu4[i].x, u0);  u1 = fmaf(x1, wu4[i].y, u1);
                u0 = fmaf(x2, wu4[i].z, u0);  u1 = fmaf(x3, wu4[i].w, u1);
                n0 = fmaf(x0, wn4[i].x, n0);  n1 = fmaf(x1, wn4[i].y, n1);
                n0 = fmaf(x2, wn4[i].z, n0);  n1 = fmaf(x3, wn4[i].w, n1);
            }
        }
        __syncthreads();
    }

    float r  = sigmoid_acc((r0 + r1) + bih[d]       + bhh[d]);
    float u  = sigmoid_acc((u0 + u1) + bih[512 + d] + bhh[512 + d]);
    float nn = tanhf((n0 + n1) + bih[1024 + d] + r * bhh[1024 + d]);
    float h  = (1.0f - u) * nn;

    int o = m * 512 + d;
    H[o] = h;
    out_h[o] = h;
    HA[o] = h + action[o];
}

// ---------------------------------------------------------------------------
// K4: dec (96 blk) + rs1 (64 blk) + CC (128 blk) = 288 blocks
// ---------------------------------------------------------------------------
__global__ void __launch_bounds__(256) k4_kernel(
    const float* __restrict__ H, const float* __restrict__ HA,
    const float* __restrict__ dec_w, const float* __restrict__ dec_b,
    float* __restrict__ pred,
    const float* __restrict__ rs_w1, const float* __restrict__ rs_b1,
    float* __restrict__ R1,
    const float* __restrict__ sc_w1, float* __restrict__ CC)
{
    __shared__ float pool[32 * 129];
    int b = blockIdx.x;
    if (b < 96) {
        gemm_dev<32, 256, false>(pool, b,       H,  512, dec_w,  512,    0, dec_b,  pred, 768, 512);
    } else if (b < 160) {
        gemm_dev<32, 256, true >(pool, b - 96,  H,  512, rs_w1,  512,    0, rs_b1,  R1,   512, 512);
    } else {
        gemm_dev<32, 256, false>(pool, b - 160, HA, 512, sc_w1, 1536, 1024, nullptr,CC,  1024, 512);
    }
}

// ---------------------------------------------------------------------------
// K5: rs2 (64 blk) + score (128 blk) = 192 blocks
// Score: graph[i,j] += (1/32)*sigmoid( sum_d w2*gelu(x) + b2 ), x=CC[b]+EA[i]+EB[j]
// gelu(x) ~ 0.5x + 0.5x*tanh(t(x)); both halves accumulated in-loop.
// Block: fixed b, 16 i-rows, all 64 j. 8 warps x 2 rows; lane does j, j+32.
// ---------------------------------------------------------------------------
#define SC_POOL (128*65 + 16*128 + 128)

__global__ void __launch_bounds__(256) k5_kernel(
    const float* __restrict__ R1, const float* __restrict__ rs_w2,
    const float* __restrict__ rs_b2, float* __restrict__ reason,
    const float* __restrict__ EA, const float* __restrict__ EB,
    const float* __restrict__ CC,
    const float* __restrict__ w2, const float* __restrict__ b2p,
    float* __restrict__ graph)
{
    __shared__ float pool[SC_POOL];
    int blk = blockIdx.x;
    if (blk < 64) {
        gemm_dev<32, 256, false>(pool, blk, R1, 512, rs_w2, 512, 0, rs_b2, reason, 512, 512);
        return;
    }
    const int sb = blk - 64;
    const int b  = sb >> 2;
    const int i0 = (sb & 3) * 16;

    float (*sE)[65]  = (float (*)[65])pool;                 // [dd][j]
    float (*sA)[128] = (float (*)[128])(pool + 128 * 65);   // [r][dd]
    float* sW = pool + 128 * 65 + 16 * 128;

    const int warp = threadIdx.x >> 5;
    const int lane = threadIdx.x & 31;
    const int ra = warp * 2, rb = warp * 2 + 1;

    float acc0a = 0.f, acc0b = 0.f, acc1a = 0.f, acc1b = 0.f;
    float lin0a = 0.f, lin0b = 0.f, lin1a = 0.f, lin1b = 0.f;

    const float C0 = 0.79788456080286536f;
    const float C1 = 0.03567740813636141f;

    for (int d0 = 0; d0 < 1024; d0 += 128) {
        for (int idx = threadIdx.x; idx < 64 * 128; idx += 256) {
            int j = idx >> 7, dd = idx & 127;
            sE[dd][j] = EB[j * 1024 + d0 + dd];
        }
        for (int idx = threadIdx.x; idx < 16 * 128; idx += 256) {
            int r = idx >> 7, dd = idx & 127;
            sA[r][dd] = EA[(i0 + r) * 1024 + d0 + dd] + CC[b * 1024 + d0 + dd];
        }
        if (threadIdx.x < 128) sW[threadIdx.x] = 0.5f * w2[d0 + threadIdx.x];
        __syncthreads();

        #pragma unroll 4
        for (int dd = 0; dd < 128; dd++) {
            float ea = sE[dd][lane];
            float eb = sE[dd][lane + 32];
            float w  = sW[dd];
            float a0 = sA[ra][dd];
            float a1 = sA[rb][dd];

            float x0a = a0 + ea, x0b = a0 + eb;
            float x1a = a1 + ea, x1b = a1 + eb;

            float t0a = x0a * fmaf(C1, x0a * x0a, C0);
            float t0b = x0b * fmaf(C1, x0b * x0b, C0);
            float t1a = x1a * fmaf(C1, x1a * x1a, C0);
            float t1b = x1b * fmaf(C1, x1b * x1b, C0);

            float h0a = tanh_approx(t0a);
            float h0b = tanh_approx(t0b);
            float h1a = tanh_approx(t1a);
            float h1b = tanh_approx(t1b);

            float wx0a = w * x0a, wx0b = w * x0b;
            float wx1a = w * x1a, wx1b = w * x1b;

            acc0a = fmaf(wx0a, h0a, acc0a);  lin0a += wx0a;
            acc0b = fmaf(wx0b, h0b, acc0b);  lin0b += wx0b;
            acc1a = fmaf(wx1a, h1a, acc1a);  lin1a += wx1a;
            acc1b = fmaf(wx1b, h1b, acc1b);  lin1b += wx1b;
        }
        __syncthreads();
    }

    const float b2 = b2p[0];
    float s0a = sigmoid_acc(acc0a + lin0a + b2) * (1.0f / 32.0f);
    float s0b = sigmoid_acc(acc0b + lin0b + b2) * (1.0f / 32.0f);
    float s1a = sigmoid_acc(acc1a + lin1a + b2) * (1.0f / 32.0f);
    float s1b = sigmoid_acc(acc1b + lin1b + b2) * (1.0f / 32.0f);

    atomicAdd(&graph[(i0 + ra) * 64 + lane],      s0a);
    atomicAdd(&graph[(i0 + ra) * 64 + lane + 32], s0b);
    atomicAdd(&graph[(i0 + rb) * 64 + lane],      s1a);
    atomicAdd(&graph[(i0 + rb) * 64 + lane + 32], s1b);
}

// ---------------------------------------------------------------------------
extern "C" void kernel_launch(void* const* d_in, const int* in_sizes, int n_in,
                              void* d_out, int out_size)
{
    float* S = nullptr;
    cudaGetSymbolAddress((void**)&S, g_scratch);

    const float* obs     = (const float*)d_in[0];
    const float* action  = (const float*)d_in[1];
    const float* embed   = (const float*)d_in[2];
    const float* sc_w1   = (const float*)d_in[3];
    const float* sc_b1   = (const float*)d_in[4];
    const float* sc_w2   = (const float*)d_in[5];
    const float* sc_b2   = (const float*)d_in[6];
    const float* enc_w1  = (const float*)d_in[7];
    const float* enc_b1  = (const float*)d_in[8];
    const float* enc_w2  = (const float*)d_in[9];
    const float* enc_b2  = (const float*)d_in[10];
    const float* gru_wih = (const float*)d_in[11];
    // d_in[12] gru_whh unused (h0 == 0)
    const float* gru_bih = (const float*)d_in[13];
    const float* gru_bhh = (const float*)d_in[14];
    const float* dec_w   = (const float*)d_in[15];
    const float* dec_b   = (const float*)d_in[16];
    const float* rs_w1   = (const float*)d_in[17];
    const float* rs_b1   = (const float*)d_in[18];
    const float* rs_w2   = (const float*)d_in[19];
    const float* rs_b2   = (const float*)d_in[20];

    float* out        = (float*)d_out;
    float* out_h      = out;
    float* out_pred   = out + 16384;
    float* out_graph  = out + 16384 + 24576;
    float* out_reason = out + 16384 + 24576 + 4096;

    float* T1 = S + OFF_T1;
    float* Z  = S + OFF_Z;
    float* H  = S + OFF_H;
    float* HA = S + OFF_HA;
    float* CC = S + OFF_CC;
    float* EA = S + OFF_EA;
    float* EB = S + OFF_EB;
    float* R1 = S + OFF_R1;

    k1_kernel<<<641, 256>>>(obs, enc_w1, enc_b1, T1, embed, sc_w1, sc_b1, EA, EB, out_graph);
    k2_kernel<<<128, 128>>>(T1, enc_w2, enc_b2, Z);
    k3_kernel<<<128, 128>>>(Z, action, gru_wih, gru_bih, gru_bhh, H, HA, out_h);
    k4_kernel<<<288, 256>>>(H, HA, dec_w, dec_b, out_pred, rs_w1, rs_b1, R1, sc_w1, CC);
    k5_kernel<<<192, 256>>>(R1, rs_w2, rs_b2, out_reason, EA, EB, CC, sc_w2, sc_b2, out_graph);
}